// round 13
// baseline (speedup 1.0000x reference)
#include <cuda_runtime.h>
#include <math.h>
#include <stdint.h>

#define KDIM 256
#define DDIM 128
#define BB 4
#define TT 1024
#define NG 8
#define NITER 100
#define NSQ 12
#define LAMBDA 0.01f
#define REGV 0.01f
#define NTOT (BB*KDIM*TT)
#define NCTA 128
#define NT 512

// ======================= device scratch =======================
__device__ float g_DtD[KDIM*KDIM];
__device__ float g_GG[DDIM*DDIM];
__device__ float g_M[2][DDIM*DDIM];
__device__ float g_scale[NSQ+1];
__device__ float g_Linv, g_lambd;
__device__ float g_xb[2][NTOT];
__device__ float g_l1[2][NTOT];
__device__ float g_gsum[NITER][NG];
__device__ unsigned g_barcnt, g_bargen;

__device__ __forceinline__ void atomicMaxPosF(float* a, float v){
    atomicMax((int*)a, __float_as_int(v));
}
// packed fp32x2 FMA (Blackwell baseline PTX)
#define FMA2(d,a,bb) asm("fma.rn.f32x2 %0, %1, %2, %0;" : "+l"(d) : "l"(a), "l"(bb))
#define SPLAT2(d,f)  asm("mov.b64 %0, {%1,%1};" : "=l"(d) : "f"(f))
#define UNPK2(lo,hi,s) asm("mov.b64 {%0,%1}, %2;" : "=f"(lo), "=f"(hi) : "l"(s))

// software grid barrier (128 co-resident CTAs, 1/SM)
__device__ __forceinline__ void gbar(){
    __syncthreads();
    if (threadIdx.x==0){
        __threadfence();
        unsigned gen = *(volatile unsigned*)&g_bargen;
        if (atomicAdd(&g_barcnt,1u)==NCTA-1u){
            g_barcnt = 0u;
            __threadfence();
            atomicAdd(&g_bargen,1u);
        } else {
            while (*(volatile unsigned*)&g_bargen == gen) __nanosleep(64);
        }
    }
    __syncthreads();
}

// ---------------- init ----------------
__global__ void k_init(){
    int i=threadIdx.x;
    for(int f=i; f<NITER*NG; f+=blockDim.x) ((float*)g_gsum)[f]=0.f;
    if(i<=NSQ) g_scale[i]=0.f;
    if(i==0){ g_barcnt=0u; g_bargen=0u; }
}

// ======================= persistent kernel =======================
#define SA_F   (KDIM*DDIM)     // 32768 floats: A^T half  [j=0..255][klocal=0..127]
#define SDTY_F (DDIM*64)       // 8192  floats: DtY tile  [klocal][tlocal]
#define SB_F   (2*16*64)       // 2048  floats: B double buffer
#define SMEM_BYTES ((SA_F+SDTY_F+SB_F+16)*4)

__global__ void __launch_bounds__(NT,1) k_persist(
    const float* __restrict__ Dict, const float* __restrict__ inp,
    const float* __restrict__ x0, float* __restrict__ out)
{
    extern __shared__ float smf[];
    float* sA   = smf;
    float* sDtY = smf + SA_F;
    float* sB   = smf + SA_F + SDTY_F;
    float* sc   = smf + SA_F + SDTY_F + SB_F;

    int tid=threadIdx.x, tx=tid&15, ty=tid>>4, w=tid>>5, lane=tid&31;
    int jl=tid>>5, tc=(tid&31)*2;              // staging coords: row jl, col pair tc
    int tb=blockIdx.x<<6, kh=blockIdx.y, kbase=kh<<7, b=blockIdx.z;
    int cid = blockIdx.x + (blockIdx.y<<4) + (blockIdx.z<<5);

    // ---------- S1a: DtD rows 2cid,2cid+1 (first 256 threads) ----------
    if(tid<KDIM){
        #pragma unroll
        for(int r=0;r<2;r++){
            int i = cid*2+r, j=tid;
            float a0=0.f,a1=0.f,a2=0.f,a3=0.f;
            #pragma unroll 8
            for(int d=0;d<DDIM;d+=4){
                a0+=Dict[(d  )*KDIM+i]*Dict[(d  )*KDIM+j];
                a1+=Dict[(d+1)*KDIM+i]*Dict[(d+1)*KDIM+j];
                a2+=Dict[(d+2)*KDIM+i]*Dict[(d+2)*KDIM+j];
                a3+=Dict[(d+3)*KDIM+i]*Dict[(d+3)*KDIM+j];
            }
            g_DtD[i*KDIM+j]=(a0+a1)+(a2+a3);
        }
    }
    // ---------- S1b: GG row cid ----------
    if(tid<DDIM){
        int i=cid, j=tid;
        float a0=0.f,a1=0.f,a2=0.f,a3=0.f;
        #pragma unroll 8
        for(int k=0;k<KDIM;k+=4){
            a0+=Dict[i*KDIM+k  ]*Dict[j*KDIM+k  ];
            a1+=Dict[i*KDIM+k+1]*Dict[j*KDIM+k+1];
            a2+=Dict[i*KDIM+k+2]*Dict[j*KDIM+k+2];
            a3+=Dict[i*KDIM+k+3]*Dict[j*KDIM+k+3];
        }
        float acc=(a0+a1)+(a2+a3);
        g_GG[i*DDIM+j]=acc;
        float m=fabsf(acc);
        #pragma unroll
        for(int o=16;o>0;o>>=1) m=fmaxf(m,__shfl_xor_sync(0xffffffffu,m,o));
        if((tid&31)==0) atomicMaxPosF(&g_scale[0], m);
    }
    // ---------- S1c: DtY tile -> sDtY (rows ty*4+i, cols tx*4) ----------
    {
        float da[4][4];
        #pragma unroll
        for(int i=0;i<4;i++){
            #pragma unroll
            for(int q=0;q<4;q++) da[i][q]=0.f;
        }
        for(int d=0; d<DDIM; d++){
            float4 a0=*(const float4*)&Dict[d*KDIM + kbase + ty*4];
            float4 bv=*(const float4*)&inp[((size_t)b*DDIM + d)*TT + tb + tx*4];
            da[0][0]+=a0.x*bv.x; da[0][1]+=a0.x*bv.y; da[0][2]+=a0.x*bv.z; da[0][3]+=a0.x*bv.w;
            da[1][0]+=a0.y*bv.x; da[1][1]+=a0.y*bv.y; da[1][2]+=a0.y*bv.z; da[1][3]+=a0.y*bv.w;
            da[2][0]+=a0.z*bv.x; da[2][1]+=a0.z*bv.y; da[2][2]+=a0.z*bv.z; da[2][3]+=a0.z*bv.w;
            da[3][0]+=a0.w*bv.x; da[3][1]+=a0.w*bv.y; da[3][2]+=a0.w*bv.z; da[3][3]+=a0.w*bv.w;
        }
        #pragma unroll
        for(int i=0;i<4;i++)
            *(float4*)&sDtY[(ty*4+i)*64 + tx*4] = make_float4(da[i][0],da[i][1],da[i][2],da[i][3]);
    }
    gbar();

    // ---------- S2: 12 normalized squarings of GG ----------
    for(int s=0;s<NSQ;s++){
        const float* __restrict__ in = (s==0)? g_GG : g_M[(s-1)&1];
        float* __restrict__ outm = g_M[s&1];
        if(tid<DDIM){
            float inv = 1.0f/__ldcg(&g_scale[s]);
            int i=cid, j=tid;
            float a0=0.f,a1=0.f,a2=0.f,a3=0.f;
            #pragma unroll 8
            for(int p=0;p<DDIM;p+=4){
                a0+=__ldcg(&in[i*DDIM+p  ])*__ldcg(&in[(p  )*DDIM+j]);
                a1+=__ldcg(&in[i*DDIM+p+1])*__ldcg(&in[(p+1)*DDIM+j]);
                a2+=__ldcg(&in[i*DDIM+p+2])*__ldcg(&in[(p+2)*DDIM+j]);
                a3+=__ldcg(&in[i*DDIM+p+3])*__ldcg(&in[(p+3)*DDIM+j]);
            }
            float acc=((a0+a1)+(a2+a3))*inv*inv;
            outm[i*DDIM+j]=acc;
            float m=fabsf(acc);
            #pragma unroll
            for(int o=16;o>0;o>>=1) m=fmaxf(m,__shfl_xor_sync(0xffffffffu,m,o));
            if((tid&31)==0) atomicMaxPosF(&g_scale[s+1], m);
        }
        gbar();
    }

    // ---------- S3: Rayleigh quotient (CTA 0) ----------
    if(cid==0){
        float* v=sB; float* red=sB+128; int* rid=(int*)(sB+256);
        const float* __restrict__ Mf = g_M[(NSQ-1)&1];
        int j=tid;
        if(j<DDIM){ red[j]=__ldcg(&Mf[j*DDIM+j]); rid[j]=j; }
        __syncthreads();
        for(int s2=DDIM/2;s2>0;s2>>=1){
            if(j<s2 && red[j+s2]>red[j]){ red[j]=red[j+s2]; rid[j]=rid[j+s2]; }
            __syncthreads();
        }
        int jstar=rid[0];
        __syncthreads();
        if(j<DDIM) v[j]=__ldcg(&Mf[j*DDIM+jstar]);
        __syncthreads();
        float u=0.f;
        if(j<DDIM){
            #pragma unroll 8
            for(int p=0;p<DDIM;p++) u += __ldcg(&g_GG[j*DDIM+p])*v[p];
            red[j]=u*v[j];
        }
        __syncthreads();
        for(int s2=DDIM/2;s2>0;s2>>=1){ if(j<s2) red[j]+=red[j+s2]; __syncthreads(); }
        float NUM=red[0];
        __syncthreads();
        if(j<DDIM) red[j]=v[j]*v[j];
        __syncthreads();
        for(int s2=DDIM/2;s2>0;s2>>=1){ if(j<s2) red[j]+=red[j+s2]; __syncthreads(); }
        if(j==0){
            float L = NUM/red[0];
            g_Linv = 1.0f/L;
            g_lambd = LAMBDA/L;
        }
    }
    gbar();

    // ---------- S4: build persistent A^T half in SMEM ----------
    float Linv=__ldcg(&g_Linv), lam=__ldcg(&g_lambd);
    for(int f=tid; f<SA_F; f+=NT){
        int j=f>>7, kl=f&127;
        int col = kbase+kl;
        sA[f] = ((j==col)?1.f:0.f) - __ldcg(&g_DtD[j*KDIM+col])*Linv;
    }
    __syncthreads();

    // ---------- iterations ----------
    float mom=1.f, coef=0.f;
    float vv[4][4];
    int writer = (kh==0);

    for(int it=0; it<NITER; it++){
        int first = (it==0);
        const float* __restrict__ l1r = g_l1[(it+1)&1];
        float* __restrict__ l1w       = g_l1[it&1];
        const float* __restrict__ xr  = first ? x0 : g_xb[(it+1)&1];
        float* __restrict__ xw        = g_xb[it&1];

        if(tid<NG){
            float s = first ? 1.f : __ldcg(&g_gsum[it-1][tid]);
            sc[tid] = (s>0.f)? fmaxf(0.f, 1.f - REGV/sqrtf(s)) : 0.f;
        }
        if(!first){
            float nm = 0.5f + 0.5f*sqrtf(1.f + 4.f*mom*mom);
            coef = (mom-1.f)/nm; mom = nm;
        }

        uint64_t acc2[2][4];
        #pragma unroll
        for(int pp=0;pp<2;pp++){
            #pragma unroll
            for(int q=0;q<4;q++) acc2[pp][q]=0ull;
        }

        float2 rl1, rxo;
        // load chunk 0 (row jl, cols tc..tc+1)
        {
            size_t idx=((size_t)(b*KDIM+jl))*TT + tb + tc;
            rxo = __ldcg((const float2*)&xr[idx]);
            if(!first) rl1 = __ldcg((const float2*)&l1r[idx]);
        }
        __syncthreads();   // sc visible
        // store chunk 0 -> buf0
        {
            float2 v;
            if(first){ v=rxo; }
            else{
                float scale = sc[0];   // jg = jl < 16 -> group 0
                float nx0=rl1.x*scale, nx1=rl1.y*scale;
                v.x=nx0+(nx0-rxo.x)*coef; v.y=nx1+(nx1-rxo.y)*coef;
                if(writer){
                    size_t idx=((size_t)(b*KDIM+jl))*TT + tb + tc;
                    *(float2*)&xw[idx]=make_float2(nx0,nx1);
                }
            }
            *(float2*)&sB[(0*16+jl)*64 + tc] = v;
        }
        // load chunk 1
        {
            size_t idx=((size_t)(b*KDIM+16+jl))*TT + tb + tc;
            rxo = __ldcg((const float2*)&xr[idx]);
            if(!first) rl1 = __ldcg((const float2*)&l1r[idx]);
        }
        __syncthreads();   // buf0 visible

        for(int c=0;c<16;c++){
            if(c<15){
                int cc=c+1, jg=cc*16+jl, bsel=cc&1;
                float2 v;
                if(first){ v=rxo; }
                else{
                    float scale = sc[jg>>5];
                    float nx0=rl1.x*scale, nx1=rl1.y*scale;
                    v.x=nx0+(nx0-rxo.x)*coef; v.y=nx1+(nx1-rxo.y)*coef;
                    if(writer){
                        size_t idx=((size_t)(b*KDIM+jg))*TT + tb + tc;
                        *(float2*)&xw[idx]=make_float2(nx0,nx1);
                    }
                }
                *(float2*)&sB[(bsel*16+jl)*64 + tc] = v;
            }
            if(c<14){
                int jg=(c+2)*16+jl;
                size_t idx=((size_t)(b*KDIM+jg))*TT + tb + tc;
                rxo = __ldcg((const float2*)&xr[idx]);
                if(!first) rl1 = __ldcg((const float2*)&l1r[idx]);
            }
            // ---- f32x2 FMA over chunk c: rows ty*4..+3 (2 packed pairs), cols tx*4..+3 ----
            {
                int base=(c&1)*1024;
                #pragma unroll
                for(int p=0;p<16;p++){
                    ulonglong2 A01=*(const ulonglong2*)&sA[(c*16+p)*128 + ty*4];
                    float4 bv=*(const float4*)&sB[base + p*64 + tx*4];
                    uint64_t s0,s1,s2,s3;
                    SPLAT2(s0,bv.x); SPLAT2(s1,bv.y); SPLAT2(s2,bv.z); SPLAT2(s3,bv.w);
                    FMA2(acc2[0][0],A01.x,s0); FMA2(acc2[0][1],A01.x,s1);
                    FMA2(acc2[0][2],A01.x,s2); FMA2(acc2[0][3],A01.x,s3);
                    FMA2(acc2[1][0],A01.y,s0); FMA2(acc2[1][1],A01.y,s1);
                    FMA2(acc2[1][2],A01.y,s2); FMA2(acc2[1][3],A01.y,s3);
                }
            }
            if(c<15) __syncthreads();
        }

        // ---- epilogue: unpack, + DtY*Linv, prox, write l1, group ssq ----
        #pragma unroll
        for(int pp=0;pp<2;pp++){
            #pragma unroll
            for(int q=0;q<4;q++){
                float lo,hi; UNPK2(lo,hi,acc2[pp][q]);
                vv[2*pp][q]=lo; vv[2*pp+1][q]=hi;
            }
        }
        float ssq=0.f;
        #pragma unroll
        for(int i=0;i<4;i++){
            int rl=ty*4+i;
            float4 dty=*(const float4*)&sDtY[rl*64 + tx*4];
            float s0=vv[i][0]+dty.x*Linv;
            float s1=vv[i][1]+dty.y*Linv;
            float s2=vv[i][2]+dty.z*Linv;
            float s3=vv[i][3]+dty.w*Linv;
            float v0=fmaxf(s0-lam,0.f)+fminf(s0+lam,0.f);
            float v1=fmaxf(s1-lam,0.f)+fminf(s1+lam,0.f);
            float v2=fmaxf(s2-lam,0.f)+fminf(s2+lam,0.f);
            float v3=fmaxf(s3-lam,0.f)+fminf(s3+lam,0.f);
            vv[i][0]=v0; vv[i][1]=v1; vv[i][2]=v2; vv[i][3]=v3;
            *(float4*)&l1w[((size_t)(b*KDIM+kbase+rl))*TT + tb + tx*4] = make_float4(v0,v1,v2,v3);
            ssq += v0*v0+v1*v1+v2*v2+v3*v3;
        }
        // warp w covers rows 8w..8w+7 -> group kh*4 + (w>>2)
        #pragma unroll
        for(int o=16;o>0;o>>=1) ssq += __shfl_xor_sync(0xffffffffu, ssq, o);
        if(lane==0) atomicAdd(&g_gsum[it][kh*4 + (w>>2)], ssq);
        gbar();
    }

    // ---------- final: out = l1_99 * group_scale(gsum_99) ----------
    if(tid<NG){
        float s = __ldcg(&g_gsum[NITER-1][tid]);
        sc[tid] = (s>0.f)? fmaxf(0.f, 1.f - REGV/sqrtf(s)) : 0.f;
    }
    __syncthreads();
    #pragma unroll
    for(int i=0;i<4;i++){
        int rl=ty*4+i, row=kbase+rl;
        float scale = sc[row>>5];
        *(float4*)&out[((size_t)(b*KDIM+row))*TT + tb + tx*4] =
            make_float4(vv[i][0]*scale, vv[i][1]*scale, vv[i][2]*scale, vv[i][3]*scale);
    }
}

// ======================= host launcher =======================
extern "C" void kernel_launch(void* const* d_in, const int* in_sizes, int n_in,
                              void* d_out, int out_size) {
    const float *Dict=nullptr, *inp=nullptr, *x0=nullptr;
    for(int i=0;i<n_in;i++){
        if      (in_sizes[i]==KDIM*DDIM)  Dict=(const float*)d_in[i];
        else if (in_sizes[i]==BB*DDIM*TT) inp =(const float*)d_in[i];
        else if (in_sizes[i]==NTOT)       x0  =(const float*)d_in[i];
    }
    float* out=(float*)d_out;

    // idempotent, unconditionally (fresh container/context must not skip it)
    cudaFuncSetAttribute(k_persist, cudaFuncAttributeMaxDynamicSharedMemorySize, SMEM_BYTES);

    k_init<<<1,1024>>>();
    k_persist<<<dim3(16,2,4), NT, SMEM_BYTES>>>(Dict, inp, x0, out);
}

// round 16
// speedup vs baseline: 1.1260x; 1.1260x over previous
#include <cuda_runtime.h>
#include <math.h>
#include <stdint.h>

#define KDIM 256
#define DDIM 128
#define BB 4
#define TT 1024
#define NG 8
#define NITER 100
#define NSQ 12
#define LAMBDA 0.01f
#define REGV 0.01f
#define NTOT (BB*KDIM*TT)
#define NCTA 128
#define NT 128

// ======================= device scratch =======================
__device__ float g_DtD[KDIM*KDIM];
__device__ float g_GG[DDIM*DDIM];
__device__ float g_M[2][DDIM*DDIM];
__device__ float g_scale[NSQ+1];
__device__ float g_Linv, g_lambd;
__device__ float g_xb[2][NTOT];
__device__ float g_l1[2][NTOT];
__device__ float g_gsum[NITER][NG];
__device__ unsigned g_barcnt, g_bargen;

__device__ __forceinline__ void atomicMaxPosF(float* a, float v){
    atomicMax((int*)a, __float_as_int(v));
}
#define FMA2(d,a,bb) asm("fma.rn.f32x2 %0, %1, %2, %0;" : "+l"(d) : "l"(a), "l"(bb))
#define SPLAT2(d,f)  asm("mov.b64 %0, {%1,%1};" : "=l"(d) : "f"(f))
#define UNPK2(lo,hi,s) asm("mov.b64 {%0,%1}, %2;" : "=f"(lo), "=f"(hi) : "l"(s))

// software grid barrier (128 co-resident CTAs, 1/SM)
__device__ __forceinline__ void gbar(){
    __syncthreads();
    if (threadIdx.x==0){
        __threadfence();
        unsigned gen = *(volatile unsigned*)&g_bargen;
        if (atomicAdd(&g_barcnt,1u)==NCTA-1u){
            g_barcnt = 0u;
            __threadfence();
            atomicAdd(&g_bargen,1u);
        } else {
            while (*(volatile unsigned*)&g_bargen == gen) __nanosleep(64);
        }
    }
    __syncthreads();
}

// ---------------- init ----------------
__global__ void k_init(){
    int i=threadIdx.x;
    for(int f=i; f<NITER*NG; f+=blockDim.x) ((float*)g_gsum)[f]=0.f;
    if(i<=NSQ) g_scale[i]=0.f;
    if(i==0){ g_barcnt=0u; g_bargen=0u; }
}

// ======================= persistent kernel =======================
#define SA_F   (KDIM*DDIM)     // 32768 floats: A^T half [j=0..255][klocal=0..127]
#define SDTY_F (DDIM*64)       // 8192  floats: DtY tile [klocal][tlocal]
#define SB_F   (2*16*64)       // 2048  floats: B double buffer
#define SMEM_BYTES ((SA_F+SDTY_F+SB_F+16)*4)

__global__ void __launch_bounds__(NT,1) k_persist(
    const float* __restrict__ Dict, const float* __restrict__ inp,
    const float* __restrict__ x0, float* __restrict__ out)
{
    extern __shared__ float smf[];
    float* sA   = smf;
    float* sDtY = smf + SA_F;
    float* sB   = smf + SA_F + SDTY_F;
    float* sc   = smf + SA_F + SDTY_F + SB_F;

    int tid=threadIdx.x, w=tid>>5, lane=tid&31;
    int trow=tid>>3, tcol=tid&7;                 // FMA tile: rows trow*8..+7, cols tcol*8..+7
    int scol=tcol*8;                             // staging: row trow, cols scol..+7
    int tb=blockIdx.x<<6, kh=blockIdx.y, kbase=kh<<7, b=blockIdx.z;
    int cid = blockIdx.x + (blockIdx.y<<4) + (blockIdx.z<<5);

    // ---------- S1a: DtD rows 2cid,2cid+1 ----------
    #pragma unroll
    for(int r=0;r<2;r++){
        int i = cid*2+r;
        #pragma unroll
        for(int hf=0; hf<2; hf++){
            int j = tid + hf*128;
            float a0=0.f,a1=0.f,a2=0.f,a3=0.f;
            #pragma unroll 8
            for(int d=0;d<DDIM;d+=4){
                a0+=Dict[(d  )*KDIM+i]*Dict[(d  )*KDIM+j];
                a1+=Dict[(d+1)*KDIM+i]*Dict[(d+1)*KDIM+j];
                a2+=Dict[(d+2)*KDIM+i]*Dict[(d+2)*KDIM+j];
                a3+=Dict[(d+3)*KDIM+i]*Dict[(d+3)*KDIM+j];
            }
            g_DtD[i*KDIM+j]=(a0+a1)+(a2+a3);
        }
    }
    // ---------- S1b: GG row cid ----------
    {
        int i=cid, j=tid;
        float a0=0.f,a1=0.f,a2=0.f,a3=0.f;
        #pragma unroll 8
        for(int k=0;k<KDIM;k+=4){
            a0+=Dict[i*KDIM+k  ]*Dict[j*KDIM+k  ];
            a1+=Dict[i*KDIM+k+1]*Dict[j*KDIM+k+1];
            a2+=Dict[i*KDIM+k+2]*Dict[j*KDIM+k+2];
            a3+=Dict[i*KDIM+k+3]*Dict[j*KDIM+k+3];
        }
        float acc=(a0+a1)+(a2+a3);
        g_GG[i*DDIM+j]=acc;
        float m=fabsf(acc);
        #pragma unroll
        for(int o=16;o>0;o>>=1) m=fmaxf(m,__shfl_xor_sync(0xffffffffu,m,o));
        if((tid&31)==0) atomicMaxPosF(&g_scale[0], m);
    }
    // ---------- S1c: DtY tile -> sDtY (per-thread 8x8) ----------
    {
        float da[8][8];
        #pragma unroll
        for(int i=0;i<8;i++)
            #pragma unroll
            for(int q=0;q<8;q++) da[i][q]=0.f;
        for(int d=0; d<DDIM; d++){
            float4 a0=*(const float4*)&Dict[d*KDIM + kbase + trow*8];
            float4 a1=*(const float4*)&Dict[d*KDIM + kbase + trow*8 + 4];
            float4 b0=*(const float4*)&inp[((size_t)b*DDIM + d)*TT + tb + scol];
            float4 b1=*(const float4*)&inp[((size_t)b*DDIM + d)*TT + tb + scol + 4];
            float av[8]={a0.x,a0.y,a0.z,a0.w,a1.x,a1.y,a1.z,a1.w};
            float bv[8]={b0.x,b0.y,b0.z,b0.w,b1.x,b1.y,b1.z,b1.w};
            #pragma unroll
            for(int i=0;i<8;i++)
                #pragma unroll
                for(int q=0;q<8;q++) da[i][q]+=av[i]*bv[q];
        }
        #pragma unroll
        for(int i=0;i<8;i++){
            *(float4*)&sDtY[(trow*8+i)*64 + scol]     = make_float4(da[i][0],da[i][1],da[i][2],da[i][3]);
            *(float4*)&sDtY[(trow*8+i)*64 + scol + 4] = make_float4(da[i][4],da[i][5],da[i][6],da[i][7]);
        }
    }
    gbar();

    // ---------- S2: 12 normalized squarings of GG ----------
    for(int s=0;s<NSQ;s++){
        const float* __restrict__ in = (s==0)? g_GG : g_M[(s-1)&1];
        float* __restrict__ outm = g_M[s&1];
        float inv = 1.0f/__ldcg(&g_scale[s]);
        int i=cid, j=tid;
        float a0=0.f,a1=0.f,a2=0.f,a3=0.f;
        #pragma unroll 8
        for(int p=0;p<DDIM;p+=4){
            a0+=__ldcg(&in[i*DDIM+p  ])*__ldcg(&in[(p  )*DDIM+j]);
            a1+=__ldcg(&in[i*DDIM+p+1])*__ldcg(&in[(p+1)*DDIM+j]);
            a2+=__ldcg(&in[i*DDIM+p+2])*__ldcg(&in[(p+2)*DDIM+j]);
            a3+=__ldcg(&in[i*DDIM+p+3])*__ldcg(&in[(p+3)*DDIM+j]);
        }
        float acc=((a0+a1)+(a2+a3))*inv*inv;
        outm[i*DDIM+j]=acc;
        float m=fabsf(acc);
        #pragma unroll
        for(int o=16;o>0;o>>=1) m=fmaxf(m,__shfl_xor_sync(0xffffffffu,m,o));
        if((tid&31)==0) atomicMaxPosF(&g_scale[s+1], m);
        gbar();
    }

    // ---------- S3: Rayleigh quotient (CTA 0) ----------
    if(cid==0){
        float* v=sB; float* red=sB+128; int* rid=(int*)(sB+256);
        const float* __restrict__ Mf = g_M[(NSQ-1)&1];
        int j=tid;
        red[j]=__ldcg(&Mf[j*DDIM+j]); rid[j]=j;
        __syncthreads();
        for(int s2=DDIM/2;s2>0;s2>>=1){
            if(j<s2 && red[j+s2]>red[j]){ red[j]=red[j+s2]; rid[j]=rid[j+s2]; }
            __syncthreads();
        }
        int jstar=rid[0];
        __syncthreads();
        v[j]=__ldcg(&Mf[j*DDIM+jstar]);
        __syncthreads();
        float u=0.f;
        #pragma unroll 8
        for(int p=0;p<DDIM;p++) u += __ldcg(&g_GG[j*DDIM+p])*v[p];
        red[j]=u*v[j];
        __syncthreads();
        for(int s2=DDIM/2;s2>0;s2>>=1){ if(j<s2) red[j]+=red[j+s2]; __syncthreads(); }
        float NUM=red[0];
        __syncthreads();
        red[j]=v[j]*v[j];
        __syncthreads();
        for(int s2=DDIM/2;s2>0;s2>>=1){ if(j<s2) red[j]+=red[j+s2]; __syncthreads(); }
        if(j==0){
            float L = NUM/red[0];
            g_Linv = 1.0f/L;
            g_lambd = LAMBDA/L;
        }
    }
    gbar();

    // ---------- S4: build persistent A^T half in SMEM ----------
    float Linv=__ldcg(&g_Linv), lam=__ldcg(&g_lambd);
    for(int f=tid; f<SA_F; f+=NT){
        int j=f>>7, kl=f&127;
        int col = kbase+kl;
        sA[f] = ((j==col)?1.f:0.f) - __ldcg(&g_DtD[j*KDIM+col])*Linv;
    }
    __syncthreads();

    // ---------- iterations ----------
    float mom=1.f, coef=0.f;
    int writer = (kh==0);

    for(int it=0; it<NITER; it++){
        int first = (it==0);
        const float* __restrict__ l1r = g_l1[(it+1)&1];
        float* __restrict__ l1w       = g_l1[it&1];
        const float* __restrict__ xr  = first ? x0 : g_xb[(it+1)&1];
        float* __restrict__ xw        = g_xb[it&1];

        if(tid<NG){
            float s = first ? 1.f : __ldcg(&g_gsum[it-1][tid]);
            sc[tid] = (s>0.f)? fmaxf(0.f, 1.f - REGV/sqrtf(s)) : 0.f;
        }
        if(!first){
            float nm = 0.5f + 0.5f*sqrtf(1.f + 4.f*mom*mom);
            coef = (mom-1.f)/nm; mom = nm;
        }

        uint64_t acc2[4][8];
        #pragma unroll
        for(int mi=0;mi<4;mi++)
            #pragma unroll
            for(int q=0;q<8;q++) acc2[mi][q]=0ull;

        float4 rxo0,rxo1,rl10,rl11;
        // load chunk 0 (row trow, cols scol..+7)
        {
            size_t idx=((size_t)(b*KDIM+trow))*TT + tb + scol;
            rxo0=__ldcg((const float4*)&xr[idx]); rxo1=__ldcg((const float4*)&xr[idx+4]);
            if(!first){ rl10=__ldcg((const float4*)&l1r[idx]); rl11=__ldcg((const float4*)&l1r[idx+4]); }
        }
        __syncthreads();   // sc visible
        // store chunk 0 -> buf0
        {
            float4 v0,v1;
            if(first){ v0=rxo0; v1=rxo1; }
            else{
                float scale = sc[0];   // trow<16 -> group 0
                float n0=rl10.x*scale,n1=rl10.y*scale,n2=rl10.z*scale,n3=rl10.w*scale;
                float n4=rl11.x*scale,n5=rl11.y*scale,n6=rl11.z*scale,n7=rl11.w*scale;
                v0.x=n0+(n0-rxo0.x)*coef; v0.y=n1+(n1-rxo0.y)*coef;
                v0.z=n2+(n2-rxo0.z)*coef; v0.w=n3+(n3-rxo0.w)*coef;
                v1.x=n4+(n4-rxo1.x)*coef; v1.y=n5+(n5-rxo1.y)*coef;
                v1.z=n6+(n6-rxo1.z)*coef; v1.w=n7+(n7-rxo1.w)*coef;
                if(writer){
                    size_t idx=((size_t)(b*KDIM+trow))*TT + tb + scol;
                    *(float4*)&xw[idx]=make_float4(n0,n1,n2,n3);
                    *(float4*)&xw[idx+4]=make_float4(n4,n5,n6,n7);
                }
            }
            *(float4*)&sB[(0*16+trow)*64 + scol]   = v0;
            *(float4*)&sB[(0*16+trow)*64 + scol+4] = v1;
        }
        // load chunk 1
        {
            size_t idx=((size_t)(b*KDIM+16+trow))*TT + tb + scol;
            rxo0=__ldcg((const float4*)&xr[idx]); rxo1=__ldcg((const float4*)&xr[idx+4]);
            if(!first){ rl10=__ldcg((const float4*)&l1r[idx]); rl11=__ldcg((const float4*)&l1r[idx+4]); }
        }
        __syncthreads();   // buf0 visible

        for(int c=0;c<16;c++){
            if(c<15){
                int cc=c+1, jg=cc*16+trow, bsel=cc&1;
                float4 v0,v1;
                if(first){ v0=rxo0; v1=rxo1; }
                else{
                    float scale = sc[jg>>5];
                    float n0=rl10.x*scale,n1=rl10.y*scale,n2=rl10.z*scale,n3=rl10.w*scale;
                    float n4=rl11.x*scale,n5=rl11.y*scale,n6=rl11.z*scale,n7=rl11.w*scale;
                    v0.x=n0+(n0-rxo0.x)*coef; v0.y=n1+(n1-rxo0.y)*coef;
                    v0.z=n2+(n2-rxo0.z)*coef; v0.w=n3+(n3-rxo0.w)*coef;
                    v1.x=n4+(n4-rxo1.x)*coef; v1.y=n5+(n5-rxo1.y)*coef;
                    v1.z=n6+(n6-rxo1.z)*coef; v1.w=n7+(n7-rxo1.w)*coef;
                    if(writer){
                        size_t idx=((size_t)(b*KDIM+jg))*TT + tb + scol;
                        *(float4*)&xw[idx]=make_float4(n0,n1,n2,n3);
                        *(float4*)&xw[idx+4]=make_float4(n4,n5,n6,n7);
                    }
                }
                *(float4*)&sB[(bsel*16+trow)*64 + scol]   = v0;
                *(float4*)&sB[(bsel*16+trow)*64 + scol+4] = v1;
            }
            if(c<14){
                int jg=(c+2)*16+trow;
                size_t idx=((size_t)(b*KDIM+jg))*TT + tb + scol;
                rxo0=__ldcg((const float4*)&xr[idx]); rxo1=__ldcg((const float4*)&xr[idx+4]);
                if(!first){ rl10=__ldcg((const float4*)&l1r[idx]); rl11=__ldcg((const float4*)&l1r[idx+4]); }
            }
            // ---- f32x2 FMA over chunk c: rows trow*8..+7 (4 pairs) x cols tcol*8..+7 ----
            {
                int base=(c&1)*1024;
                #pragma unroll
                for(int p=0;p<16;p++){
                    const float* ar=&sA[(c*16+p)*128 + trow*8];
                    ulonglong2 A01=*(const ulonglong2*)ar;
                    ulonglong2 A23=*(const ulonglong2*)(ar+4);
                    float4 b0=*(const float4*)&sB[base + p*64 + tcol*8];
                    float4 b1=*(const float4*)&sB[base + p*64 + tcol*8 + 4];
                    uint64_t s0,s1,s2,s3,s4,s5,s6,s7;
                    SPLAT2(s0,b0.x); SPLAT2(s1,b0.y); SPLAT2(s2,b0.z); SPLAT2(s3,b0.w);
                    SPLAT2(s4,b1.x); SPLAT2(s5,b1.y); SPLAT2(s6,b1.z); SPLAT2(s7,b1.w);
                    FMA2(acc2[0][0],A01.x,s0); FMA2(acc2[0][1],A01.x,s1); FMA2(acc2[0][2],A01.x,s2); FMA2(acc2[0][3],A01.x,s3);
                    FMA2(acc2[0][4],A01.x,s4); FMA2(acc2[0][5],A01.x,s5); FMA2(acc2[0][6],A01.x,s6); FMA2(acc2[0][7],A01.x,s7);
                    FMA2(acc2[1][0],A01.y,s0); FMA2(acc2[1][1],A01.y,s1); FMA2(acc2[1][2],A01.y,s2); FMA2(acc2[1][3],A01.y,s3);
                    FMA2(acc2[1][4],A01.y,s4); FMA2(acc2[1][5],A01.y,s5); FMA2(acc2[1][6],A01.y,s6); FMA2(acc2[1][7],A01.y,s7);
                    FMA2(acc2[2][0],A23.x,s0); FMA2(acc2[2][1],A23.x,s1); FMA2(acc2[2][2],A23.x,s2); FMA2(acc2[2][3],A23.x,s3);
                    FMA2(acc2[2][4],A23.x,s4); FMA2(acc2[2][5],A23.x,s5); FMA2(acc2[2][6],A23.x,s6); FMA2(acc2[2][7],A23.x,s7);
                    FMA2(acc2[3][0],A23.y,s0); FMA2(acc2[3][1],A23.y,s1); FMA2(acc2[3][2],A23.y,s2); FMA2(acc2[3][3],A23.y,s3);
                    FMA2(acc2[3][4],A23.y,s4); FMA2(acc2[3][5],A23.y,s5); FMA2(acc2[3][6],A23.y,s6); FMA2(acc2[3][7],A23.y,s7);
                }
            }
            if(c<15) __syncthreads();
        }

        // ---- epilogue: unpack per row, + DtY*Linv, prox, write l1, group ssq ----
        float ssq=0.f;
        #pragma unroll
        for(int i=0;i<8;i++){
            int mi=i>>1, part=i&1;
            float vr[8];
            #pragma unroll
            for(int q=0;q<8;q++){
                float lo,hi; UNPK2(lo,hi,acc2[mi][q]);
                vr[q] = part? hi : lo;
            }
            int rl=trow*8+i;
            float4 d0=*(const float4*)&sDtY[rl*64 + scol];
            float4 d1=*(const float4*)&sDtY[rl*64 + scol + 4];
            float dv[8]={d0.x,d0.y,d0.z,d0.w,d1.x,d1.y,d1.z,d1.w};
            float o[8];
            #pragma unroll
            for(int q=0;q<8;q++){
                float s = vr[q] + dv[q]*Linv;
                float v = fmaxf(s-lam,0.f)+fminf(s+lam,0.f);
                o[q]=v; ssq += v*v;
            }
            size_t ob=((size_t)(b*KDIM+kbase+rl))*TT + tb + scol;
            *(float4*)&l1w[ob]   = make_float4(o[0],o[1],o[2],o[3]);
            *(float4*)&l1w[ob+4] = make_float4(o[4],o[5],o[6],o[7]);
        }
        // warp w covers rows 32w..32w+31 -> group kh*4 + w
        #pragma unroll
        for(int o2=16;o2>0;o2>>=1) ssq += __shfl_xor_sync(0xffffffffu, ssq, o2);
        if(lane==0) atomicAdd(&g_gsum[it][kh*4 + w], ssq);
        gbar();
    }

    // ---------- final: out = l1_99 * group_scale(gsum_99) (re-read l1 from L2) ----------
    if(tid<NG){
        float s = __ldcg(&g_gsum[NITER-1][tid]);
        sc[tid] = (s>0.f)? fmaxf(0.f, 1.f - REGV/sqrtf(s)) : 0.f;
    }
    __syncthreads();
    const float* __restrict__ l1f = g_l1[(NITER-1)&1];
    #pragma unroll
    for(int i=0;i<8;i++){
        int rl=trow*8+i, row=kbase+rl;
        float scale = sc[row>>5];
        size_t ob=((size_t)(b*KDIM+row))*TT + tb + scol;
        float4 a=__ldcg((const float4*)&l1f[ob]);
        float4 c2=__ldcg((const float4*)&l1f[ob+4]);
        *(float4*)&out[ob]   = make_float4(a.x*scale,a.y*scale,a.z*scale,a.w*scale);
        *(float4*)&out[ob+4] = make_float4(c2.x*scale,c2.y*scale,c2.z*scale,c2.w*scale);
    }
}

// ======================= host launcher =======================
extern "C" void kernel_launch(void* const* d_in, const int* in_sizes, int n_in,
                              void* d_out, int out_size) {
    const float *Dict=nullptr, *inp=nullptr, *x0=nullptr;
    for(int i=0;i<n_in;i++){
        if      (in_sizes[i]==KDIM*DDIM)  Dict=(const float*)d_in[i];
        else if (in_sizes[i]==BB*DDIM*TT) inp =(const float*)d_in[i];
        else if (in_sizes[i]==NTOT)       x0  =(const float*)d_in[i];
    }
    float* out=(float*)d_out;

    cudaFuncSetAttribute(k_persist, cudaFuncAttributeMaxDynamicSharedMemorySize, SMEM_BYTES);

    k_init<<<1,1024>>>();
    k_persist<<<dim3(16,2,4), NT, SMEM_BYTES>>>(Dict, inp, x0, out);
}